// round 1
// baseline (speedup 1.0000x reference)
#include <cuda_runtime.h>

#define DIM     512
#define HEADS   8
#define DH      64
#define BATCH   8
#define NWIN    64
#define WSZ     64
#define NTOK    (BATCH * NWIN * WSZ)   // 32768

// Scratch (allocation-free rule: __device__ globals)
__device__ float g_qkv[(size_t)NTOK * 3 * DIM];   // ~201 MB
__device__ float g_attn[(size_t)NTOK * DIM];      // ~67 MB

// ---------------------------------------------------------------------------
// SGEMM: C[M,N] = A[M,K] @ B[K,N] (+ bias broadcast over rows)
// Requires M%128==0, N%128==0, K%8==0. 128x128 tile, BK=8, 256 thr, 8x8 micro.
// ---------------------------------------------------------------------------
__global__ __launch_bounds__(256) void sgemm128(
    const float* __restrict__ A, const float* __restrict__ B,
    const float* __restrict__ bias, float* __restrict__ C,
    int M, int N, int K)
{
    __shared__ float As[8][128];   // transposed A tile: As[k][m]
    __shared__ float Bs[8][128];   // Bs[k][n]

    const int tid = threadIdx.x;
    const int tx  = tid & 15;      // 16 column-threads (8 cols each)
    const int ty  = tid >> 4;      // 16 row-threads   (8 rows each)
    const int bm  = blockIdx.y * 128;
    const int bn  = blockIdx.x * 128;

    // A loader: 128 rows x 8 cols = 256 float4 -> 1 per thread
    const int arow = tid >> 1;
    const int acol = (tid & 1) * 4;
    // B loader: 8 rows x 128 cols = 256 float4 -> 1 per thread
    const int brow = tid >> 5;
    const int bcol = (tid & 31) * 4;

    const float* Aptr = A + (size_t)(bm + arow) * K + acol;
    const float* Bptr = B + (size_t)brow * N + bn + bcol;

    float acc[8][8];
    #pragma unroll
    for (int i = 0; i < 8; i++)
        #pragma unroll
        for (int j = 0; j < 8; j++) acc[i][j] = 0.f;

    for (int k0 = 0; k0 < K; k0 += 8) {
        float4 a4 = *(const float4*)Aptr;
        float4 b4 = *(const float4*)Bptr;
        As[acol + 0][arow] = a4.x;
        As[acol + 1][arow] = a4.y;
        As[acol + 2][arow] = a4.z;
        As[acol + 3][arow] = a4.w;
        *(float4*)&Bs[brow][bcol] = b4;
        __syncthreads();

        #pragma unroll
        for (int k = 0; k < 8; k++) {
            float ra[8], rb[8];
            *(float4*)&ra[0] = *(const float4*)&As[k][ty * 8];
            *(float4*)&ra[4] = *(const float4*)&As[k][ty * 8 + 4];
            *(float4*)&rb[0] = *(const float4*)&Bs[k][tx * 8];
            *(float4*)&rb[4] = *(const float4*)&Bs[k][tx * 8 + 4];
            #pragma unroll
            for (int i = 0; i < 8; i++)
                #pragma unroll
                for (int j = 0; j < 8; j++)
                    acc[i][j] += ra[i] * rb[j];
        }
        __syncthreads();
        Aptr += 8;
        Bptr += (size_t)8 * N;
    }

    #pragma unroll
    for (int i = 0; i < 8; i++) {
        const int row = bm + ty * 8 + i;
        float* crow = C + (size_t)row * N + bn + tx * 8;
        #pragma unroll
        for (int j = 0; j < 8; j += 4) {
            float4 v;
            v.x = acc[i][j];   v.y = acc[i][j + 1];
            v.z = acc[i][j + 2]; v.w = acc[i][j + 3];
            if (bias) {
                const float* bp = bias + bn + tx * 8 + j;
                v.x += bp[0]; v.y += bp[1]; v.z += bp[2]; v.w += bp[3];
            }
            *(float4*)(crow + j) = v;
        }
    }
}

// ---------------------------------------------------------------------------
// Window attention: one block per (b, h, n). 64x64x64 per window.
// qkv row layout for token t: [r(3)][h(8)][d(64)]  (c = r*512 + h*64 + d)
// Output in [B,H,NW,W,dh] linear order == flat [32768,512] for the proj GEMM.
// ---------------------------------------------------------------------------
__global__ __launch_bounds__(256) void window_attn(
    const float* __restrict__ qkv, float* __restrict__ out)
{
    __shared__ float Qs[64][64];   // Q rows; later overwritten with P (softmax(S))
    __shared__ float Kt[64][64];   // K transposed: Kt[d][k]
    __shared__ float Vs[64][64];   // V rows

    const int tid  = threadIdx.x;
    const int idx  = blockIdx.x;
    const int n    = idx % NWIN;
    const int h    = (idx / NWIN) % HEADS;
    const int b    = idx / (NWIN * HEADS);
    const int tx   = tid & 15;     // 16 col-threads (4 each)
    const int ty   = tid >> 4;     // 16 row-threads (4 each)

    const size_t tokbase = ((size_t)(b * NWIN + n) * WSZ) * (3 * DIM);

    // Load Q, K, V (each 64 rows x 64 floats, rows contiguous in gmem)
    for (int i = tid; i < 64 * 16; i += 256) {
        const int row = i >> 4;
        const int c4  = (i & 15) * 4;
        const size_t src = tokbase + (size_t)row * (3 * DIM) + h * DH + c4;
        float4 q4 = *(const float4*)(qkv + src);
        float4 k4 = *(const float4*)(qkv + src + DIM);
        float4 v4 = *(const float4*)(qkv + src + 2 * DIM);
        *(float4*)&Qs[row][c4] = q4;
        Kt[c4 + 0][row] = k4.x;
        Kt[c4 + 1][row] = k4.y;
        Kt[c4 + 2][row] = k4.z;
        Kt[c4 + 3][row] = k4.w;
        *(float4*)&Vs[row][c4] = v4;
    }
    __syncthreads();

    // S = Q K^T * scale  (4x4 micro-tile per thread)
    const float scale = 0.125f;  // dh^-0.5 = 64^-0.5
    float sacc[4][4];
    #pragma unroll
    for (int i = 0; i < 4; i++)
        #pragma unroll
        for (int j = 0; j < 4; j++) sacc[i][j] = 0.f;

    #pragma unroll 8
    for (int d = 0; d < 64; d++) {
        float ra[4];
        float4 rb4 = *(const float4*)&Kt[d][tx * 4];
        const float rb[4] = {rb4.x, rb4.y, rb4.z, rb4.w};
        #pragma unroll
        for (int i = 0; i < 4; i++) ra[i] = Qs[ty * 4 + i][d];
        #pragma unroll
        for (int i = 0; i < 4; i++)
            #pragma unroll
            for (int j = 0; j < 4; j++)
                sacc[i][j] += ra[i] * rb[j];
    }
    __syncthreads();   // all Q reads done; safe to overwrite Qs with S

    #pragma unroll
    for (int i = 0; i < 4; i++) {
        float4 v;
        v.x = sacc[i][0] * scale; v.y = sacc[i][1] * scale;
        v.z = sacc[i][2] * scale; v.w = sacc[i][3] * scale;
        *(float4*)&Qs[ty * 4 + i][tx * 4] = v;
    }
    __syncthreads();

    // Row softmax: 8 warps x 8 rows each, 2 cols per lane
    {
        const int lane = tid & 31;
        const int wid  = tid >> 5;
        for (int r = 0; r < 8; r++) {
            const int row = wid * 8 + r;
            float v0 = Qs[row][lane];
            float v1 = Qs[row][lane + 32];
            float m = fmaxf(v0, v1);
            #pragma unroll
            for (int o = 16; o > 0; o >>= 1)
                m = fmaxf(m, __shfl_xor_sync(0xffffffffu, m, o));
            float e0 = expf(v0 - m);
            float e1 = expf(v1 - m);
            float s = e0 + e1;
            #pragma unroll
            for (int o = 16; o > 0; o >>= 1)
                s += __shfl_xor_sync(0xffffffffu, s, o);
            const float inv = 1.f / s;
            Qs[row][lane]      = e0 * inv;
            Qs[row][lane + 32] = e1 * inv;
        }
    }
    __syncthreads();

    // O = P V  (P lives in Qs)
    float oacc[4][4];
    #pragma unroll
    for (int i = 0; i < 4; i++)
        #pragma unroll
        for (int j = 0; j < 4; j++) oacc[i][j] = 0.f;

    #pragma unroll 8
    for (int k = 0; k < 64; k++) {
        float ra[4];
        float4 rb4 = *(const float4*)&Vs[k][tx * 4];
        const float rb[4] = {rb4.x, rb4.y, rb4.z, rb4.w};
        #pragma unroll
        for (int i = 0; i < 4; i++) ra[i] = Qs[ty * 4 + i][k];
        #pragma unroll
        for (int i = 0; i < 4; i++)
            #pragma unroll
            for (int j = 0; j < 4; j++)
                oacc[i][j] += ra[i] * rb[j];
    }

    // Write O to [B,H,NW,W,dh] linear layout
    const size_t obase = (((size_t)(b * HEADS + h) * NWIN + n) * WSZ) * DH;
    #pragma unroll
    for (int i = 0; i < 4; i++) {
        float4 v;
        v.x = oacc[i][0]; v.y = oacc[i][1];
        v.z = oacc[i][2]; v.w = oacc[i][3];
        *(float4*)(out + obase + (size_t)(ty * 4 + i) * DH + tx * 4) = v;
    }
}

// ---------------------------------------------------------------------------
extern "C" void kernel_launch(void* const* d_in, const int* in_sizes, int n_in,
                              void* d_out, int out_size)
{
    const float* x      = (const float*)d_in[0];  // [8,64,64,512]
    const float* w_qkv  = (const float*)d_in[1];  // [512,1536]
    const float* w_proj = (const float*)d_in[2];  // [512,512]
    const float* b_proj = (const float*)d_in[3];  // [512]
    float* out = (float*)d_out;                   // [8,64,64,512]

    float* qkv;  cudaGetSymbolAddress((void**)&qkv,  g_qkv);
    float* attn; cudaGetSymbolAddress((void**)&attn, g_attn);

    // 1) qkv = x @ w_qkv          (32768 x 1536 x 512)
    {
        dim3 grid(1536 / 128, NTOK / 128);
        sgemm128<<<grid, 256>>>(x, w_qkv, nullptr, qkv, NTOK, 3 * DIM, DIM);
    }
    // 2) per-window attention -> attn in [B,H,NW,W,dh] linear order
    {
        window_attn<<<BATCH * HEADS * NWIN, 256>>>(qkv, attn);
    }
    // 3) out = attn_flat @ w_proj + b_proj   (32768 x 512 x 512)
    {
        dim3 grid(512 / 128, NTOK / 128);
        sgemm128<<<grid, 256>>>(attn, w_proj, b_proj, out, NTOK, DIM, DIM);
    }
}

// round 2
// speedup vs baseline: 2.3719x; 2.3719x over previous
#include <cuda_runtime.h>

#define DIM     512
#define HEADS   8
#define DH      64
#define BATCH   8
#define NWIN    64
#define WSZ     64
#define NTOK    (BATCH * NWIN * WSZ)   // 32768

// Scratch (allocation-free rule: __device__ globals)
__device__ float g_qkv[(size_t)NTOK * 3 * DIM];   // ~201 MB
__device__ float g_attn[(size_t)NTOK * DIM];      // ~67 MB

// ---------------------------------------------------------------------------
// tf32 helpers
// ---------------------------------------------------------------------------
__device__ __forceinline__ unsigned f2tf(float x) {
    unsigned r;
    asm("cvt.rna.tf32.f32 %0, %1;" : "=r"(r) : "f"(x));
    return r;
}

__device__ __forceinline__ void mma_tf32(float c[4], const unsigned a[4],
                                         const unsigned b[2]) {
    asm volatile(
        "mma.sync.aligned.m16n8k8.row.col.f32.tf32.tf32.f32 "
        "{%0,%1,%2,%3}, {%4,%5,%6,%7}, {%8,%9}, {%0,%1,%2,%3};"
        : "+f"(c[0]), "+f"(c[1]), "+f"(c[2]), "+f"(c[3])
        : "r"(a[0]), "r"(a[1]), "r"(a[2]), "r"(a[3]), "r"(b[0]), "r"(b[1]));
}

// ---------------------------------------------------------------------------
// tf32 GEMM: C[M,N] = A[M,K] @ B[K,N] (+bias). M%128==0, N%128==0, K%32==0.
// 256 threads / 8 warps. Warp tile 32x64 = 2 (m16) x 8 (n8) mma frags.
// Smem strides 36 / 136 => conflict-free fragment LDS (banks 4r+c / 8k+n).
// ---------------------------------------------------------------------------
__global__ __launch_bounds__(256) void gemm_tf32(
    const float* __restrict__ A, const float* __restrict__ B,
    const float* __restrict__ bias, float* __restrict__ C,
    int M, int N, int K)
{
    __shared__ unsigned As[128][36];
    __shared__ unsigned Bs[32][136];

    const int tid  = threadIdx.x;
    const int lane = tid & 31;
    const int wid  = tid >> 5;
    const int wm   = (wid & 3) * 32;    // warp row offset in tile
    const int wn   = (wid >> 2) * 64;   // warp col offset in tile
    const int bm   = blockIdx.y * 128;
    const int bn   = blockIdx.x * 128;
    const int g    = lane >> 2;         // octet row/col
    const int q    = lane & 3;          // quad

    const int ar = tid >> 3, ac = (tid & 7) * 4;    // A loader: 32 rows x 8 f4
    const int br = tid >> 5, bc = (tid & 31) * 4;   // B loader: 8 rows x 32 f4

    float acc[2][8][4];
    #pragma unroll
    for (int i = 0; i < 2; i++)
        #pragma unroll
        for (int j = 0; j < 8; j++)
            #pragma unroll
            for (int k = 0; k < 4; k++) acc[i][j][k] = 0.f;

    for (int k0 = 0; k0 < K; k0 += 32) {
        #pragma unroll
        for (int i = 0; i < 4; i++) {
            const int row = ar + i * 32;
            float4 v = *(const float4*)(A + (size_t)(bm + row) * K + k0 + ac);
            uint4 u = make_uint4(f2tf(v.x), f2tf(v.y), f2tf(v.z), f2tf(v.w));
            *(uint4*)&As[row][ac] = u;
        }
        #pragma unroll
        for (int i = 0; i < 4; i++) {
            const int row = br + i * 8;
            float4 v = *(const float4*)(B + (size_t)(k0 + row) * N + bn + bc);
            uint4 u = make_uint4(f2tf(v.x), f2tf(v.y), f2tf(v.z), f2tf(v.w));
            *(uint4*)&Bs[row][bc] = u;
        }
        __syncthreads();

        #pragma unroll
        for (int ks = 0; ks < 4; ks++) {
            const int k8 = ks * 8;
            unsigned afr[2][4], bfr[8][2];
            #pragma unroll
            for (int mt = 0; mt < 2; mt++) {
                const int r = wm + mt * 16 + g;
                afr[mt][0] = As[r][k8 + q];
                afr[mt][1] = As[r + 8][k8 + q];
                afr[mt][2] = As[r][k8 + q + 4];
                afr[mt][3] = As[r + 8][k8 + q + 4];
            }
            #pragma unroll
            for (int nt = 0; nt < 8; nt++) {
                const int c = wn + nt * 8 + g;
                bfr[nt][0] = Bs[k8 + q][c];
                bfr[nt][1] = Bs[k8 + q + 4][c];
            }
            #pragma unroll
            for (int mt = 0; mt < 2; mt++)
                #pragma unroll
                for (int nt = 0; nt < 8; nt++)
                    mma_tf32(acc[mt][nt], afr[mt], bfr[nt]);
        }
        __syncthreads();
    }

    // Epilogue
    #pragma unroll
    for (int nt = 0; nt < 8; nt++) {
        const int col = bn + wn + nt * 8 + q * 2;
        float b0 = 0.f, b1 = 0.f;
        if (bias) { b0 = bias[col]; b1 = bias[col + 1]; }
        #pragma unroll
        for (int mt = 0; mt < 2; mt++) {
            const int r0 = bm + wm + mt * 16 + g;
            float2 v0 = make_float2(acc[mt][nt][0] + b0, acc[mt][nt][1] + b1);
            float2 v1 = make_float2(acc[mt][nt][2] + b0, acc[mt][nt][3] + b1);
            *(float2*)(C + (size_t)r0 * N + col) = v0;
            *(float2*)(C + (size_t)(r0 + 8) * N + col) = v1;
        }
    }
}

// ---------------------------------------------------------------------------
// Window attention (tf32 mma). One 128-thread block per (b,h,n) window.
// Warp w owns rows 16w..16w+15. S = QK^T -> register softmax -> P overwrites
// Q's smem rows (warp-private, no sync) -> V (prefetched to regs during S)
// overwrites K's buffer -> O = P V -> direct [B,H,NW,W,dh] store.
// ---------------------------------------------------------------------------
__global__ __launch_bounds__(128) void window_attn_tf32(
    const float* __restrict__ qkv, float* __restrict__ out)
{
    __shared__ unsigned Qs[64][68];   // Q, then P (tf32 bits)
    __shared__ unsigned KVs[64][68];  // K, then V (tf32 bits)

    const int tid  = threadIdx.x;
    const int lane = tid & 31;
    const int w    = tid >> 5;
    const int g    = lane >> 2;
    const int q4   = lane & 3;

    const int idx = blockIdx.x;
    const int n   = idx & 63;
    const int h   = (idx >> 6) & 7;
    const int b   = idx >> 9;
    const size_t tokbase = ((size_t)(b * NWIN + n) * WSZ) * (3 * DIM);

    // Load Q,K to smem (tf32); prefetch V to registers.
    float4 vpre[8];
    #pragma unroll
    for (int i = 0; i < 8; i++) {
        const int lin = i * 128 + tid;
        const int row = lin >> 4;
        const int c4  = (lin & 15) * 4;
        const size_t src = tokbase + (size_t)row * (3 * DIM) + h * DH + c4;
        vpre[i] = *(const float4*)(qkv + src + 2 * DIM);
        float4 qv = *(const float4*)(qkv + src);
        float4 kv = *(const float4*)(qkv + src + DIM);
        *(uint4*)&Qs[row][c4]  = make_uint4(f2tf(qv.x), f2tf(qv.y), f2tf(qv.z), f2tf(qv.w));
        *(uint4*)&KVs[row][c4] = make_uint4(f2tf(kv.x), f2tf(kv.y), f2tf(kv.z), f2tf(kv.w));
    }
    __syncthreads();

    // S = Q K^T  (warp: rows 16w..16w+15; 8 n-frags; 8 k-steps)
    float sacc[8][4];
    #pragma unroll
    for (int nt = 0; nt < 8; nt++)
        #pragma unroll
        for (int j = 0; j < 4; j++) sacc[nt][j] = 0.f;

    #pragma unroll
    for (int ks = 0; ks < 8; ks++) {
        const int k8 = ks * 8;
        unsigned a[4];
        const int r = w * 16 + g;
        a[0] = Qs[r][k8 + q4];
        a[1] = Qs[r + 8][k8 + q4];
        a[2] = Qs[r][k8 + q4 + 4];
        a[3] = Qs[r + 8][k8 + q4 + 4];
        #pragma unroll
        for (int nt = 0; nt < 8; nt++) {
            const int c = nt * 8 + g;
            unsigned bfr[2];
            bfr[0] = KVs[c][k8 + q4];
            bfr[1] = KVs[c][k8 + q4 + 4];
            mma_tf32(sacc[nt], a, bfr);
        }
    }

    // Register softmax over the two rows this thread touches.
    const float scale = 0.125f;
    float mx0 = -1e30f, mx1 = -1e30f;
    #pragma unroll
    for (int nt = 0; nt < 8; nt++) {
        #pragma unroll
        for (int j = 0; j < 4; j++) sacc[nt][j] *= scale;
        mx0 = fmaxf(mx0, fmaxf(sacc[nt][0], sacc[nt][1]));
        mx1 = fmaxf(mx1, fmaxf(sacc[nt][2], sacc[nt][3]));
    }
    mx0 = fmaxf(mx0, __shfl_xor_sync(0xffffffffu, mx0, 1));
    mx0 = fmaxf(mx0, __shfl_xor_sync(0xffffffffu, mx0, 2));
    mx1 = fmaxf(mx1, __shfl_xor_sync(0xffffffffu, mx1, 1));
    mx1 = fmaxf(mx1, __shfl_xor_sync(0xffffffffu, mx1, 2));

    float s0 = 0.f, s1 = 0.f;
    #pragma unroll
    for (int nt = 0; nt < 8; nt++) {
        sacc[nt][0] = __expf(sacc[nt][0] - mx0);
        sacc[nt][1] = __expf(sacc[nt][1] - mx0);
        sacc[nt][2] = __expf(sacc[nt][2] - mx1);
        sacc[nt][3] = __expf(sacc[nt][3] - mx1);
        s0 += sacc[nt][0] + sacc[nt][1];
        s1 += sacc[nt][2] + sacc[nt][3];
    }
    s0 += __shfl_xor_sync(0xffffffffu, s0, 1);
    s0 += __shfl_xor_sync(0xffffffffu, s0, 2);
    s1 += __shfl_xor_sync(0xffffffffu, s1, 1);
    s1 += __shfl_xor_sync(0xffffffffu, s1, 2);
    const float inv0 = 1.f / s0, inv1 = 1.f / s1;

    // P -> Qs (warp-private rows; no block sync needed for this region)
    {
        const int r = w * 16 + g;
        #pragma unroll
        for (int nt = 0; nt < 8; nt++) {
            const int col = nt * 8 + q4 * 2;
            uint2 p0 = make_uint2(f2tf(sacc[nt][0] * inv0), f2tf(sacc[nt][1] * inv0));
            uint2 p1 = make_uint2(f2tf(sacc[nt][2] * inv1), f2tf(sacc[nt][3] * inv1));
            *(uint2*)&Qs[r][col]     = p0;
            *(uint2*)&Qs[r + 8][col] = p1;
        }
    }
    __syncthreads();   // all K reads complete before V overwrites KVs

    // V regs -> KVs (tf32)
    #pragma unroll
    for (int i = 0; i < 8; i++) {
        const int lin = i * 128 + tid;
        const int row = lin >> 4;
        const int c4  = (lin & 15) * 4;
        *(uint4*)&KVs[row][c4] =
            make_uint4(f2tf(vpre[i].x), f2tf(vpre[i].y), f2tf(vpre[i].z), f2tf(vpre[i].w));
    }
    __syncthreads();

    // O = P V
    float oacc[8][4];
    #pragma unroll
    for (int nt = 0; nt < 8; nt++)
        #pragma unroll
        for (int j = 0; j < 4; j++) oacc[nt][j] = 0.f;

    #pragma unroll
    for (int ks = 0; ks < 8; ks++) {
        const int k8 = ks * 8;
        unsigned a[4];
        const int r = w * 16 + g;
        a[0] = Qs[r][k8 + q4];
        a[1] = Qs[r + 8][k8 + q4];
        a[2] = Qs[r][k8 + q4 + 4];
        a[3] = Qs[r + 8][k8 + q4 + 4];
        #pragma unroll
        for (int nt = 0; nt < 8; nt++) {
            const int c = nt * 8 + g;
            unsigned bfr[2];
            bfr[0] = KVs[k8 + q4][c];
            bfr[1] = KVs[k8 + q4 + 4][c];
            mma_tf32(oacc[nt], a, bfr);
        }
    }

    // O -> [B,H,NW,W,dh] linear layout (free reshape for proj GEMM)
    const size_t obase = (((size_t)(b * HEADS + h) * NWIN + n) * WSZ) * DH;
    const int r = w * 16 + g;
    #pragma unroll
    for (int nt = 0; nt < 8; nt++) {
        const int col = nt * 8 + q4 * 2;
        *(float2*)(out + obase + (size_t)r * DH + col) =
            make_float2(oacc[nt][0], oacc[nt][1]);
        *(float2*)(out + obase + (size_t)(r + 8) * DH + col) =
            make_float2(oacc[nt][2], oacc[nt][3]);
    }
}

// ---------------------------------------------------------------------------
extern "C" void kernel_launch(void* const* d_in, const int* in_sizes, int n_in,
                              void* d_out, int out_size)
{
    const float* x      = (const float*)d_in[0];  // [8,64,64,512]
    const float* w_qkv  = (const float*)d_in[1];  // [512,1536]
    const float* w_proj = (const float*)d_in[2];  // [512,512]
    const float* b_proj = (const float*)d_in[3];  // [512]
    float* out = (float*)d_out;                   // [8,64,64,512]

    float* qkv;  cudaGetSymbolAddress((void**)&qkv,  g_qkv);
    float* attn; cudaGetSymbolAddress((void**)&attn, g_attn);

    // 1) qkv = x @ w_qkv          (32768 x 1536 x 512)
    {
        dim3 grid((3 * DIM) / 128, NTOK / 128);
        gemm_tf32<<<grid, 256>>>(x, w_qkv, nullptr, qkv, NTOK, 3 * DIM, DIM);
    }
    // 2) per-window attention -> attn in [B,H,NW,W,dh] linear order
    {
        window_attn_tf32<<<BATCH * HEADS * NWIN, 128>>>(qkv, attn);
    }
    // 3) out = attn_flat @ w_proj + b_proj   (32768 x 512 x 512)
    {
        dim3 grid(DIM / 128, NTOK / 128);
        gemm_tf32<<<grid, 256>>>(attn, w_proj, b_proj, out, NTOK, DIM, DIM);
    }
}

// round 4
// speedup vs baseline: 3.4333x; 1.4475x over previous
#include <cuda_runtime.h>
#include <cstdint>

#define DIM     512
#define HEADS   8
#define DH      64
#define BATCH   8
#define NWIN    64
#define WSZ     64
#define NTOK    (BATCH * NWIN * WSZ)   // 32768

// Scratch (allocation-free rule: __device__ globals)
__device__ float g_qkv[(size_t)NTOK * 3 * DIM];                 // ~201 MB
__device__ float g_attn[(size_t)NTOK * DIM];                    // ~67 MB
__device__ float g_wr[(size_t)DIM * (3 * DIM) + DIM * DIM];     // 4 MB rounded weights

// ---------------------------------------------------------------------------
// helpers
// ---------------------------------------------------------------------------
__device__ __forceinline__ unsigned f2tf(float x) {
    unsigned r;
    asm("cvt.rna.tf32.f32 %0, %1;" : "=r"(r) : "f"(x));
    return r;
}

__device__ __forceinline__ uint32_t smem_u32(const void* p) {
    uint32_t a;
    asm("{ .reg .u64 t; cvta.to.shared.u64 t, %1; cvt.u32.u64 %0, t; }"
        : "=r"(a) : "l"(p));
    return a;
}

__device__ __forceinline__ void cp16(uint32_t dst, const void* src) {
    asm volatile("cp.async.cg.shared.global [%0], [%1], 16;"
                 :: "r"(dst), "l"(src) : "memory");
}

__device__ __forceinline__ void mma_tf32(float c[4], const unsigned a[4],
                                         const unsigned b[2]) {
    asm volatile(
        "mma.sync.aligned.m16n8k8.row.col.f32.tf32.tf32.f32 "
        "{%0,%1,%2,%3}, {%4,%5,%6,%7}, {%8,%9}, {%0,%1,%2,%3};"
        : "+f"(c[0]), "+f"(c[1]), "+f"(c[2]), "+f"(c[3])
        : "r"(a[0]), "r"(a[1]), "r"(a[2]), "r"(a[3]), "r"(b[0]), "r"(b[1]));
}

// ---------------------------------------------------------------------------
// tf32-round copy (weights): out[i] = rna_tf32(in[i])
// ---------------------------------------------------------------------------
__global__ void round_copy(const float* __restrict__ in, float* __restrict__ out,
                           int n4)
{
    const int i = blockIdx.x * blockDim.x + threadIdx.x;
    if (i < n4) {
        float4 v = ((const float4*)in)[i];
        uint4 u = make_uint4(f2tf(v.x), f2tf(v.y), f2tf(v.z), f2tf(v.w));
        ((uint4*)out)[i] = u;
    }
}

// ---------------------------------------------------------------------------
// cp.async double-buffered tf32 GEMM: C[M,N] = A[M,K] @ B[K,N] (+bias).
// B must be pre-rounded to tf32. A rounded after LDS (cvt.rna on fragments).
// 128x128 tile, BK=32, 2 stages, 256 threads / 8 warps (32x64 warp tiles).
// Strides: A 40 (2-way LDS conflict), B 136 (conflict-free); both 16B-aligned.
// ---------------------------------------------------------------------------
#define AS_STRIDE 40
#define BS_STRIDE 136
#define A_STAGE   (128 * AS_STRIDE)   // floats
#define B_STAGE   (32 * BS_STRIDE)
#define GEMM_SMEM ((2 * (A_STAGE + B_STAGE)) * 4)   // 75776 bytes

__global__ __launch_bounds__(256, 2) void gemm_pipe(
    const float* __restrict__ A, const float* __restrict__ B,
    const float* __restrict__ bias, float* __restrict__ C,
    int M, int N, int K)
{
    extern __shared__ __align__(16) float sm[];
    float* As = sm;                    // [2][128][40]
    float* Bs = sm + 2 * A_STAGE;      // [2][32][136]
    const uint32_t as_a = smem_u32(As);
    const uint32_t bs_a = smem_u32(Bs);

    const int tid  = threadIdx.x;
    const int lane = tid & 31;
    const int wid  = tid >> 5;
    const int wm   = (wid & 3) * 32;
    const int wn   = (wid >> 2) * 64;
    const int bm   = blockIdx.y * 128;
    const int bn   = blockIdx.x * 128;
    const int g    = lane >> 2;
    const int q    = lane & 3;

    float acc[2][8][4];
    #pragma unroll
    for (int i = 0; i < 2; i++)
        #pragma unroll
        for (int j = 0; j < 8; j++)
            #pragma unroll
            for (int k = 0; k < 4; k++) acc[i][j][k] = 0.f;

    const int NT = K >> 5;

    // ---- async stage loader ----
    auto load_stage = [&](int kt) {
        const int s  = kt & 1;
        const int k0 = kt * 32;
        #pragma unroll
        for (int i = 0; i < 4; i++) {
            const int idx = tid + i * 256;          // 0..1023
            const int row = idx >> 3;               // 0..127
            const int c4  = (idx & 7) * 4;          // 0..28
            cp16(as_a + (uint32_t)(s * A_STAGE + row * AS_STRIDE + c4) * 4,
                 A + (size_t)(bm + row) * K + k0 + c4);
        }
        #pragma unroll
        for (int i = 0; i < 4; i++) {
            const int idx = tid + i * 256;
            const int row = idx >> 5;               // 0..31
            const int c4  = (idx & 31) * 4;         // 0..124
            cp16(bs_a + (uint32_t)(s * B_STAGE + row * BS_STRIDE + c4) * 4,
                 B + (size_t)(k0 + row) * N + bn + c4);
        }
        asm volatile("cp.async.commit_group;" ::: "memory");
    };

    load_stage(0);

    for (int kt = 0; kt < NT; kt++) {
        if (kt + 1 < NT) {
            load_stage(kt + 1);
            asm volatile("cp.async.wait_group 1;" ::: "memory");
        } else {
            asm volatile("cp.async.wait_group 0;" ::: "memory");
        }
        __syncthreads();

        const float* as = As + (kt & 1) * A_STAGE;
        const float* bs = Bs + (kt & 1) * B_STAGE;

        #pragma unroll
        for (int ks = 0; ks < 4; ks++) {
            const int k8 = ks * 8;
            unsigned afr[2][4], bfr[8][2];
            #pragma unroll
            for (int mt = 0; mt < 2; mt++) {
                const int r = wm + mt * 16 + g;
                afr[mt][0] = f2tf(as[r * AS_STRIDE + k8 + q]);
                afr[mt][1] = f2tf(as[(r + 8) * AS_STRIDE + k8 + q]);
                afr[mt][2] = f2tf(as[r * AS_STRIDE + k8 + q + 4]);
                afr[mt][3] = f2tf(as[(r + 8) * AS_STRIDE + k8 + q + 4]);
            }
            #pragma unroll
            for (int nt = 0; nt < 8; nt++) {
                const int c = wn + nt * 8 + g;
                bfr[nt][0] = __float_as_uint(bs[(k8 + q) * BS_STRIDE + c]);
                bfr[nt][1] = __float_as_uint(bs[(k8 + q + 4) * BS_STRIDE + c]);
            }
            #pragma unroll
            for (int mt = 0; mt < 2; mt++)
                #pragma unroll
                for (int nt = 0; nt < 8; nt++)
                    mma_tf32(acc[mt][nt], afr[mt], bfr[nt]);
        }
        __syncthreads();
    }

    // Epilogue
    #pragma unroll
    for (int nt = 0; nt < 8; nt++) {
        const int col = bn + wn + nt * 8 + q * 2;
        float b0 = 0.f, b1 = 0.f;
        if (bias) { b0 = bias[col]; b1 = bias[col + 1]; }
        #pragma unroll
        for (int mt = 0; mt < 2; mt++) {
            const int r0 = bm + wm + mt * 16 + g;
            *(float2*)(C + (size_t)r0 * N + col) =
                make_float2(acc[mt][nt][0] + b0, acc[mt][nt][1] + b1);
            *(float2*)(C + (size_t)(r0 + 8) * N + col) =
                make_float2(acc[mt][nt][2] + b0, acc[mt][nt][3] + b1);
        }
    }
}

// ---------------------------------------------------------------------------
// Window attention (tf32 mma.sync) — unchanged (known good)
// ---------------------------------------------------------------------------
__global__ __launch_bounds__(128) void window_attn_tf32(
    const float* __restrict__ qkv, float* __restrict__ out)
{
    __shared__ unsigned Qs[64][68];
    __shared__ unsigned KVs[64][68];

    const int tid  = threadIdx.x;
    const int lane = tid & 31;
    const int w    = tid >> 5;
    const int g    = lane >> 2;
    const int q4   = lane & 3;

    const int idx = blockIdx.x;
    const int n   = idx & 63;
    const int h   = (idx >> 6) & 7;
    const int b   = idx >> 9;
    const size_t tokbase = ((size_t)(b * NWIN + n) * WSZ) * (3 * DIM);

    float4 vpre[8];
    #pragma unroll
    for (int i = 0; i < 8; i++) {
        const int lin = i * 128 + tid;
        const int row = lin >> 4;
        const int cc  = (lin & 15) * 4;
        const size_t src = tokbase + (size_t)row * (3 * DIM) + h * DH + cc;
        vpre[i] = *(const float4*)(qkv + src + 2 * DIM);
        float4 qv = *(const float4*)(qkv + src);
        float4 kv = *(const float4*)(qkv + src + DIM);
        *(uint4*)&Qs[row][cc]  = make_uint4(f2tf(qv.x), f2tf(qv.y), f2tf(qv.z), f2tf(qv.w));
        *(uint4*)&KVs[row][cc] = make_uint4(f2tf(kv.x), f2tf(kv.y), f2tf(kv.z), f2tf(kv.w));
    }
    __syncthreads();

    float sacc[8][4];
    #pragma unroll
    for (int nt = 0; nt < 8; nt++)
        #pragma unroll
        for (int j = 0; j < 4; j++) sacc[nt][j] = 0.f;

    #pragma unroll
    for (int ks = 0; ks < 8; ks++) {
        const int k8 = ks * 8;
        unsigned a[4];
        const int r = w * 16 + g;
        a[0] = Qs[r][k8 + q4];
        a[1] = Qs[r + 8][k8 + q4];
        a[2] = Qs[r][k8 + q4 + 4];
        a[3] = Qs[r + 8][k8 + q4 + 4];
        #pragma unroll
        for (int nt = 0; nt < 8; nt++) {
            const int c = nt * 8 + g;
            unsigned bfr[2];
            bfr[0] = KVs[c][k8 + q4];
            bfr[1] = KVs[c][k8 + q4 + 4];
            mma_tf32(sacc[nt], a, bfr);
        }
    }

    const float scale = 0.125f;
    float mx0 = -1e30f, mx1 = -1e30f;
    #pragma unroll
    for (int nt = 0; nt < 8; nt++) {
        #pragma unroll
        for (int j = 0; j < 4; j++) sacc[nt][j] *= scale;
        mx0 = fmaxf(mx0, fmaxf(sacc[nt][0], sacc[nt][1]));
        mx1 = fmaxf(mx1, fmaxf(sacc[nt][2], sacc[nt][3]));
    }
    mx0 = fmaxf(mx0, __shfl_xor_sync(0xffffffffu, mx0, 1));
    mx0 = fmaxf(mx0, __shfl_xor_sync(0xffffffffu, mx0, 2));
    mx1 = fmaxf(mx1, __shfl_xor_sync(0xffffffffu, mx1, 1));
    mx1 = fmaxf(mx1, __shfl_xor_sync(0xffffffffu, mx1, 2));

    float s0 = 0.f, s1 = 0.f;
    #pragma unroll
    for (int nt = 0; nt < 8; nt++) {
        sacc[nt][0] = __expf(sacc[nt][0] - mx0);
        sacc[nt][1] = __expf(sacc[nt][1] - mx0);
        sacc[nt][2] = __expf(sacc[nt][2] - mx1);
        sacc[nt][3] = __expf(sacc[nt][3] - mx1);
        s0 += sacc[nt][0] + sacc[nt][1];
        s1 += sacc[nt][2] + sacc[nt][3];
    }
    s0 += __shfl_xor_sync(0xffffffffu, s0, 1);
    s0 += __shfl_xor_sync(0xffffffffu, s0, 2);
    s1 += __shfl_xor_sync(0xffffffffu, s1, 1);
    s1 += __shfl_xor_sync(0xffffffffu, s1, 2);
    const float inv0 = 1.f / s0, inv1 = 1.f / s1;

    {
        const int r = w * 16 + g;
        #pragma unroll
        for (int nt = 0; nt < 8; nt++) {
            const int col = nt * 8 + q4 * 2;
            *(uint2*)&Qs[r][col] =
                make_uint2(f2tf(sacc[nt][0] * inv0), f2tf(sacc[nt][1] * inv0));
            *(uint2*)&Qs[r + 8][col] =
                make_uint2(f2tf(sacc[nt][2] * inv1), f2tf(sacc[nt][3] * inv1));
        }
    }
    __syncthreads();

    #pragma unroll
    for (int i = 0; i < 8; i++) {
        const int lin = i * 128 + tid;
        const int row = lin >> 4;
        const int cc  = (lin & 15) * 4;
        *(uint4*)&KVs[row][cc] =
            make_uint4(f2tf(vpre[i].x), f2tf(vpre[i].y), f2tf(vpre[i].z), f2tf(vpre[i].w));
    }
    __syncthreads();

    float oacc[8][4];
    #pragma unroll
    for (int nt = 0; nt < 8; nt++)
        #pragma unroll
        for (int j = 0; j < 4; j++) oacc[nt][j] = 0.f;

    #pragma unroll
    for (int ks = 0; ks < 8; ks++) {
        const int k8 = ks * 8;
        unsigned a[4];
        const int r = w * 16 + g;
        a[0] = Qs[r][k8 + q4];
        a[1] = Qs[r + 8][k8 + q4];
        a[2] = Qs[r][k8 + q4 + 4];
        a[3] = Qs[r + 8][k8 + q4 + 4];
        #pragma unroll
        for (int nt = 0; nt < 8; nt++) {
            const int c = nt * 8 + g;
            unsigned bfr[2];
            bfr[0] = KVs[k8 + q4][c];
            bfr[1] = KVs[k8 + q4 + 4][c];
            mma_tf32(oacc[nt], a, bfr);
        }
    }

    const size_t obase = (((size_t)(b * HEADS + h) * NWIN + n) * WSZ) * DH;
    const int r = w * 16 + g;
    #pragma unroll
    for (int nt = 0; nt < 8; nt++) {
        const int col = nt * 8 + q4 * 2;
        *(float2*)(out + obase + (size_t)r * DH + col) =
            make_float2(oacc[nt][0], oacc[nt][1]);
        *(float2*)(out + obase + (size_t)(r + 8) * DH + col) =
            make_float2(oacc[nt][2], oacc[nt][3]);
    }
}

// ---------------------------------------------------------------------------
extern "C" void kernel_launch(void* const* d_in, const int* in_sizes, int n_in,
                              void* d_out, int out_size)
{
    const float* x      = (const float*)d_in[0];  // [8,64,64,512]
    const float* w_qkv  = (const float*)d_in[1];  // [512,1536]
    const float* w_proj = (const float*)d_in[2];  // [512,512]
    const float* b_proj = (const float*)d_in[3];  // [512]
    float* out = (float*)d_out;                   // [8,64,64,512]

    float* qkv;  cudaGetSymbolAddress((void**)&qkv,  g_qkv);
    float* attn; cudaGetSymbolAddress((void**)&attn, g_attn);
    float* wr;   cudaGetSymbolAddress((void**)&wr,   g_wr);
    float* wqkv_r  = wr;                              // [512,1536] rounded
    float* wproj_r = wr + (size_t)DIM * (3 * DIM);    // [512,512] rounded

    static bool attr_set = false;
    if (!attr_set) {
        cudaFuncSetAttribute(gemm_pipe,
                             cudaFuncAttributeMaxDynamicSharedMemorySize, GEMM_SMEM);
        attr_set = true;
    }

    // 0) tf32-round the weights (4 MB, tiny)
    {
        const int n1 = DIM * 3 * DIM / 4, n2 = DIM * DIM / 4;
        round_copy<<<(n1 + 255) / 256, 256>>>(w_qkv, wqkv_r, n1);
        round_copy<<<(n2 + 255) / 256, 256>>>(w_proj, wproj_r, n2);
    }
    // 1) qkv = x @ w_qkv
    {
        dim3 grid((3 * DIM) / 128, NTOK / 128);
        gemm_pipe<<<grid, 256, GEMM_SMEM>>>(x, wqkv_r, nullptr, qkv,
                                            NTOK, 3 * DIM, DIM);
    }
    // 2) per-window attention -> [B,H,NW,W,dh] linear (free reshape)
    {
        window_attn_tf32<<<BATCH * HEADS * NWIN, 128>>>(qkv, attn);
    }
    // 3) out = attn_flat @ w_proj + b_proj
    {
        dim3 grid(DIM / 128, NTOK / 128);
        gemm_pipe<<<grid, 256, GEMM_SMEM>>>(attn, wproj_r, b_proj, out,
                                            NTOK, DIM, DIM);
    }
}

// round 7
// speedup vs baseline: 5.0009x; 1.4566x over previous
#include <cuda_runtime.h>
#include <cuda_fp16.h>
#include <cstdint>

#define DIM     512
#define HEADS   8
#define DH      64
#define BATCH   8
#define NWIN    64
#define WSZ     64
#define NTOK    (BATCH * NWIN * WSZ)   // 32768

// Scratch (allocation-free rule: __device__ globals)
__device__ __half g_xh[(size_t)NTOK * DIM];                       // 33.5 MB
__device__ __half g_qkvh[(size_t)NTOK * 3 * DIM];                 // 100 MB
__device__ __half g_attnh[(size_t)NTOK * DIM];                    // 33.5 MB
__device__ __half g_wth[(size_t)(3 * DIM) * DIM + DIM * DIM];     // 2 MB (wqkvT, wprojT)

// ---------------------------------------------------------------------------
// helpers
// ---------------------------------------------------------------------------
__device__ __forceinline__ uint32_t smem_u32(const void* p) {
    uint32_t a;
    asm("{ .reg .u64 t; cvta.to.shared.u64 t, %1; cvt.u32.u64 %0, t; }"
        : "=r"(a) : "l"(p));
    return a;
}

__device__ __forceinline__ void cp16(uint32_t dst, const void* src) {
    asm volatile("cp.async.cg.shared.global [%0], [%1], 16;"
                 :: "r"(dst), "l"(src) : "memory");
}

__device__ __forceinline__ void mma_f16(float c[4], const unsigned a[4],
                                        const unsigned b[2]) {
    asm volatile(
        "mma.sync.aligned.m16n8k16.row.col.f32.f16.f16.f32 "
        "{%0,%1,%2,%3}, {%4,%5,%6,%7}, {%8,%9}, {%0,%1,%2,%3};"
        : "+f"(c[0]), "+f"(c[1]), "+f"(c[2]), "+f"(c[3])
        : "r"(a[0]), "r"(a[1]), "r"(a[2]), "r"(a[3]), "r"(b[0]), "r"(b[1]));
}

__device__ __forceinline__ void mma_tf32(float c[4], const unsigned a[4],
                                         const unsigned b[2]) {
    asm volatile(
        "mma.sync.aligned.m16n8k8.row.col.f32.tf32.tf32.f32 "
        "{%0,%1,%2,%3}, {%4,%5,%6,%7}, {%8,%9}, {%0,%1,%2,%3};"
        : "+f"(c[0]), "+f"(c[1]), "+f"(c[2]), "+f"(c[3])
        : "r"(a[0]), "r"(a[1]), "r"(a[2]), "r"(a[3]), "r"(b[0]), "r"(b[1]));
}

// ---------------------------------------------------------------------------
// Prologue: fp32 -> fp16 convert (x), fp32 -> fp16 transpose (weights)
// ---------------------------------------------------------------------------
__global__ void f2h_copy(const float* __restrict__ in, __half* __restrict__ out,
                         int n4)
{
    const int i = blockIdx.x * blockDim.x + threadIdx.x;
    if (i < n4) {
        float4 v = ((const float4*)in)[i];
        __half2* o = (__half2*)(out + (size_t)i * 4);
        o[0] = __floats2half2_rn(v.x, v.y);
        o[1] = __floats2half2_rn(v.z, v.w);
    }
}

__global__ void transpose_h(const float* __restrict__ in,
                            __half* __restrict__ out, int R, int C)
{
    __shared__ float t[32][33];
    const int tx = threadIdx.x, ty = threadIdx.y;
    const int x = blockIdx.x * 32 + tx;
    #pragma unroll
    for (int j = 0; j < 32; j += 8)
        t[ty + j][tx] = in[(size_t)(blockIdx.y * 32 + ty + j) * C + x];
    __syncthreads();
    const int x2 = blockIdx.y * 32 + tx;
    #pragma unroll
    for (int j = 0; j < 32; j += 8)
        out[(size_t)(blockIdx.x * 32 + ty + j) * R + x2] =
            __float2half_rn(t[tx][ty + j]);
}

// ---------------------------------------------------------------------------
// fp16 GEMM: C[M,N] = A[M,K] @ Bt[N,K]^T (+bias).  A, Bt half row-major.
// 128x128 tile, BK=64, 2-stage cp.async, 256 thr / 8 warps (32x64 warp tiles).
// Smem stride 72 halves: fragment LDS conflict-free; rows 144B (16B-aligned).
// out_half: write __half2 (GEMM1) else float2+bias (GEMM2).
// ---------------------------------------------------------------------------
#define ST_H      72
#define TILE_H    (128 * ST_H)                 // halves per operand stage
#define GEMM_SMEM (2 * 2 * TILE_H * 2)         // 73728 bytes

__global__ __launch_bounds__(256, 2) void gemm_h(
    const __half* __restrict__ A, const __half* __restrict__ Bt,
    const float* __restrict__ bias, void* __restrict__ Cout,
    int M, int N, int K, int out_half)
{
    extern __shared__ __align__(16) __half smh[];
    __half* As = smh;                    // [2][128][72]
    __half* Bs = smh + 2 * TILE_H;       // [2][128][72]
    const uint32_t as_a = smem_u32(As);
    const uint32_t bs_a = smem_u32(Bs);

    const int tid  = threadIdx.x;
    const int lane = tid & 31;
    const int wid  = tid >> 5;
    const int wm   = (wid & 3) * 32;
    const int wn   = (wid >> 2) * 64;
    const int bm   = blockIdx.y * 128;
    const int bn   = blockIdx.x * 128;
    const int g    = lane >> 2;
    const int q    = lane & 3;

    float acc[2][8][4];
    #pragma unroll
    for (int i = 0; i < 2; i++)
        #pragma unroll
        for (int j = 0; j < 8; j++)
            #pragma unroll
            for (int k = 0; k < 4; k++) acc[i][j][k] = 0.f;

    const int NT = K >> 6;

    #define LOAD_STAGE(kt_)                                                     \
    do {                                                                        \
        const int s_  = (kt_) & 1;                                              \
        const int k0_ = (kt_) * 64;                                             \
        _Pragma("unroll")                                                       \
        for (int i_ = 0; i_ < 2; i_++) {                                        \
            const int idx_ = tid + i_ * 256;                                    \
            const int row_ = idx_ >> 2;                                         \
            const int c_   = (idx_ & 3) * 16;   /* halves: 0,16,32,48 */        \
            cp16(as_a + (uint32_t)(s_ * TILE_H + row_ * ST_H + c_) * 2,         \
                 A + (size_t)(bm + row_) * K + k0_ + c_);                       \
            cp16(as_a + (uint32_t)(s_ * TILE_H + row_ * ST_H + c_ + 8) * 2,     \
                 A + (size_t)(bm + row_) * K + k0_ + c_ + 8);                   \
            cp16(bs_a + (uint32_t)(s_ * TILE_H + row_ * ST_H + c_) * 2,         \
                 Bt + (size_t)(bn + row_) * K + k0_ + c_);                      \
            cp16(bs_a + (uint32_t)(s_ * TILE_H + row_ * ST_H + c_ + 8) * 2,     \
                 Bt + (size_t)(bn + row_) * K + k0_ + c_ + 8);                  \
        }                                                                       \
        asm volatile("cp.async.commit_group;" ::: "memory");                    \
    } while (0)

    LOAD_STAGE(0);

    for (int kt = 0; kt < NT; kt++) {
        if (kt + 1 < NT) {
            LOAD_STAGE(kt + 1);
            asm volatile("cp.async.wait_group 1;" ::: "memory");
        } else {
            asm volatile("cp.async.wait_group 0;" ::: "memory");
        }
        __syncthreads();

        const __half* as = As + (kt & 1) * TILE_H;
        const __half* bs = Bs + (kt & 1) * TILE_H;

        #pragma unroll
        for (int ks = 0; ks < 4; ks++) {
            const int k16 = ks * 16;
            unsigned afr[2][4], bfr[8][2];
            #pragma unroll
            for (int mt = 0; mt < 2; mt++) {
                const int r = wm + mt * 16 + g;
                afr[mt][0] = *(const unsigned*)&as[r * ST_H + k16 + 2 * q];
                afr[mt][1] = *(const unsigned*)&as[(r + 8) * ST_H + k16 + 2 * q];
                afr[mt][2] = *(const unsigned*)&as[r * ST_H + k16 + 2 * q + 8];
                afr[mt][3] = *(const unsigned*)&as[(r + 8) * ST_H + k16 + 2 * q + 8];
            }
            #pragma unroll
            for (int nt = 0; nt < 8; nt++) {
                const int c = wn + nt * 8 + g;
                bfr[nt][0] = *(const unsigned*)&bs[c * ST_H + k16 + 2 * q];
                bfr[nt][1] = *(const unsigned*)&bs[c * ST_H + k16 + 2 * q + 8];
            }
            #pragma unroll
            for (int mt = 0; mt < 2; mt++)
                #pragma unroll
                for (int nt = 0; nt < 8; nt++)
                    mma_f16(acc[mt][nt], afr[mt], bfr[nt]);
        }
        __syncthreads();
    }

    // Epilogue: C frag c0,c1 -> (row g, cols 2q,2q+1); c2,c3 -> row g+8.
    if (out_half) {
        __half* Ch = (__half*)Cout;
        #pragma unroll
        for (int nt = 0; nt < 8; nt++) {
            const int col = bn + wn + nt * 8 + 2 * q;
            #pragma unroll
            for (int mt = 0; mt < 2; mt++) {
                const int r0 = bm + wm + mt * 16 + g;
                *(__half2*)(Ch + (size_t)r0 * N + col) =
                    __floats2half2_rn(acc[mt][nt][0], acc[mt][nt][1]);
                *(__half2*)(Ch + (size_t)(r0 + 8) * N + col) =
                    __floats2half2_rn(acc[mt][nt][2], acc[mt][nt][3]);
            }
        }
    } else {
        float* Cf = (float*)Cout;
        #pragma unroll
        for (int nt = 0; nt < 8; nt++) {
            const int col = bn + wn + nt * 8 + 2 * q;
            float b0 = 0.f, b1 = 0.f;
            if (bias) { b0 = bias[col]; b1 = bias[col + 1]; }
            #pragma unroll
            for (int mt = 0; mt < 2; mt++) {
                const int r0 = bm + wm + mt * 16 + g;
                *(float2*)(Cf + (size_t)r0 * N + col) =
                    make_float2(acc[mt][nt][0] + b0, acc[mt][nt][1] + b1);
                *(float2*)(Cf + (size_t)(r0 + 8) * N + col) =
                    make_float2(acc[mt][nt][2] + b0, acc[mt][nt][3] + b1);
            }
        }
    }
}

// ---------------------------------------------------------------------------
// Window attention: half I/O, tf32 mma core (half->float is exact & tf32-clean)
// ---------------------------------------------------------------------------
__global__ __launch_bounds__(128) void window_attn_h(
    const __half* __restrict__ qkv, __half* __restrict__ out)
{
    __shared__ unsigned Qs[64][68];    // float/tf32 bits
    __shared__ unsigned KVs[64][68];

    const int tid  = threadIdx.x;
    const int lane = tid & 31;
    const int w    = tid >> 5;
    const int g    = lane >> 2;
    const int q4   = lane & 3;

    const int idx = blockIdx.x;
    const int n   = idx & 63;
    const int h   = (idx >> 6) & 7;
    const int b   = idx >> 9;
    const size_t tokbase = ((size_t)(b * NWIN + n) * WSZ) * (3 * DIM);

    // Load Q,K (half->float->smem); prefetch V (raw half) to registers.
    uint4 vpre[4];
    #pragma unroll
    for (int i = 0; i < 4; i++) {
        const int lin = i * 128 + tid;      // 0..511
        const int row = lin >> 3;           // 0..63
        const int c8  = (lin & 7) * 8;      // halves 0..56
        const __half* src = qkv + tokbase + (size_t)row * (3 * DIM) + h * DH + c8;
        uint4 qv = *(const uint4*)src;
        uint4 kv = *(const uint4*)(src + DIM);
        vpre[i]  = *(const uint4*)(src + 2 * DIM);
        const __half2* qh = (const __half2*)&qv;
        const __half2* kh = (const __half2*)&kv;
        #pragma unroll
        for (int p = 0; p < 4; p++) {
            float2 qf = __half22float2(qh[p]);
            float2 kf = __half22float2(kh[p]);
            Qs[row][c8 + 2 * p]      = __float_as_uint(qf.x);
            Qs[row][c8 + 2 * p + 1]  = __float_as_uint(qf.y);
            KVs[row][c8 + 2 * p]     = __float_as_uint(kf.x);
            KVs[row][c8 + 2 * p + 1] = __float_as_uint(kf.y);
        }
    }
    __syncthreads();

    // S = Q K^T
    float sacc[8][4];
    #pragma unroll
    for (int nt = 0; nt < 8; nt++)
        #pragma unroll
        for (int j = 0; j < 4; j++) sacc[nt][j] = 0.f;

    #pragma unroll
    for (int ks = 0; ks < 8; ks++) {
        const int k8 = ks * 8;
        unsigned a[4];
        const int r = w * 16 + g;
        a[0] = Qs[r][k8 + q4];
        a[1] = Qs[r + 8][k8 + q4];
        a[2] = Qs[r][k8 + q4 + 4];
        a[3] = Qs[r + 8][k8 + q4 + 4];
        #pragma unroll
        for (int nt = 0; nt < 8; nt++) {
            const int c = nt * 8 + g;
            unsigned bfr[2];
            bfr[0] = KVs[c][k8 + q4];
            bfr[1] = KVs[c][k8 + q4 + 4];
            mma_tf32(sacc[nt], a, bfr);
        }
    }

    // Register softmax (rows warp-private)
    const float scale = 0.125f;
    float mx0 = -1e30f, mx1 = -1e30f;
    #pragma unroll
    for (int nt = 0; nt < 8; nt++) {
        #pragma unroll
        for (int j = 0; j < 4; j++) sacc[nt][j] *= scale;
        mx0 = fmaxf(mx0, fmaxf(sacc[nt][0], sacc[nt][1]));
        mx1 = fmaxf(mx1, fmaxf(sacc[nt][2], sacc[nt][3]));
    }
    mx0 = fmaxf(mx0, __shfl_xor_sync(0xffffffffu, mx0, 1));
    mx0 = fmaxf(mx0, __shfl_xor_sync(0xffffffffu, mx0, 2));
    mx1 = fmaxf(mx1, __shfl_xor_sync(0xffffffffu, mx1, 1));
    mx1 = fmaxf(mx1, __shfl_xor_sync(0xffffffffu, mx1, 2));

    float s0 = 0.f, s1 = 0.f;
    #pragma unroll
    for (int nt = 0; nt < 8; nt++) {
        sacc[nt][0] = __expf(sacc[nt][0] - mx0);
        sacc[nt][1] = __expf(sacc[nt][1] - mx0);
        sacc[nt][2] = __expf(sacc[nt][2] - mx1);
        sacc[nt][3] = __expf(sacc[nt][3] - mx1);
        s0 += sacc[nt][0] + sacc[nt][1];
        s1 += sacc[nt][2] + sacc[nt][3];
    }
    s0 += __shfl_xor_sync(0xffffffffu, s0, 1);
    s0 += __shfl_xor_sync(0xffffffffu, s0, 2);
    s1 += __shfl_xor_sync(0xffffffffu, s1, 1);
    s1 += __shfl_xor_sync(0xffffffffu, s1, 2);
    const float inv0 = 1.f / s0, inv1 = 1.f / s1;

    // P -> Qs (warp-private rows)
    {
        const int r = w * 16 + g;
        #pragma unroll
        for (int nt = 0; nt < 8; nt++) {
            const int col = nt * 8 + q4 * 2;
            *(uint2*)&Qs[r][col] =
                make_uint2(__float_as_uint(sacc[nt][0] * inv0),
                           __float_as_uint(sacc[nt][1] * inv0));
            *(uint2*)&Qs[r + 8][col] =
                make_uint2(__float_as_uint(sacc[nt][2] * inv1),
                           __float_as_uint(sacc[nt][3] * inv1));
        }
    }
    __syncthreads();

    // V -> KVs (half->float)
    #pragma unroll
    for (int i = 0; i < 4; i++) {
        const int lin = i * 128 + tid;
        const int row = lin >> 3;
        const int c8  = (lin & 7) * 8;
        const __half2* vh = (const __half2*)&vpre[i];
        #pragma unroll
        for (int p = 0; p < 4; p++) {
            float2 vf = __half22float2(vh[p]);
            KVs[row][c8 + 2 * p]     = __float_as_uint(vf.x);
            KVs[row][c8 + 2 * p + 1] = __float_as_uint(vf.y);
        }
    }
    __syncthreads();

    // O = P V
    float oacc[8][4];
    #pragma unroll
    for (int nt = 0; nt < 8; nt++)
        #pragma unroll
        for (int j = 0; j < 4; j++) oacc[nt][j] = 0.f;

    #pragma unroll
    for (int ks = 0; ks < 8; ks++) {
        const int k8 = ks * 8;
        unsigned a[4];
        const int r = w * 16 + g;
        a[0] = Qs[r][k8 + q4];
        a[1] = Qs[r + 8][k8 + q4];
        a[2] = Qs[r][k8 + q4 + 4];
        a[3] = Qs[r + 8][k8 + q4 + 4];
        #pragma unroll
        for (int nt = 0; nt < 8; nt++) {
            const int c = nt * 8 + g;
            unsigned bfr[2];
            bfr[0] = KVs[k8 + q4][c];
            bfr[1] = KVs[k8 + q4 + 4][c];
            mma_tf32(oacc[nt], a, bfr);
        }
    }

    // O -> half, [B,H,NW,W,dh] linear layout
    const size_t obase = (((size_t)(b * HEADS + h) * NWIN + n) * WSZ) * DH;
    const int r = w * 16 + g;
    #pragma unroll
    for (int nt = 0; nt < 8; nt++) {
        const int col = nt * 8 + q4 * 2;
        *(__half2*)(out + obase + (size_t)r * DH + col) =
            __floats2half2_rn(oacc[nt][0], oacc[nt][1]);
        *(__half2*)(out + obase + (size_t)(r + 8) * DH + col) =
            __floats2half2_rn(oacc[nt][2], oacc[nt][3]);
    }
}

// ---------------------------------------------------------------------------
extern "C" void kernel_launch(void* const* d_in, const int* in_sizes, int n_in,
                              void* d_out, int out_size)
{
    const float* x      = (const float*)d_in[0];  // [8,64,64,512]
    const float* w_qkv  = (const float*)d_in[1];  // [512,1536]
    const float* w_proj = (const float*)d_in[2];  // [512,512]
    const float* b_proj = (const float*)d_in[3];  // [512]
    float* out = (float*)d_out;                   // [8,64,64,512]

    __half *xh, *qkvh, *attnh, *wth;
    cudaGetSymbolAddress((void**)&xh,    g_xh);
    cudaGetSymbolAddress((void**)&qkvh,  g_qkvh);
    cudaGetSymbolAddress((void**)&attnh, g_attnh);
    cudaGetSymbolAddress((void**)&wth,   g_wth);
    __half* wqkvT_h  = wth;                            // [1536,512]
    __half* wprojT_h = wth + (size_t)(3 * DIM) * DIM;  // [512,512]

    static bool attr_set = false;
    if (!attr_set) {
        cudaFuncSetAttribute(gemm_h,
                             cudaFuncAttributeMaxDynamicSharedMemorySize, GEMM_SMEM);
        attr_set = true;
    }

    // 0) prologue: x -> half; weights -> transposed half
    {
        const int n4 = NTOK * DIM / 4;
        f2h_copy<<<(n4 + 255) / 256, 256>>>(x, xh, n4);
        dim3 blk(32, 8);
        transpose_h<<<dim3((3 * DIM) / 32, DIM / 32), blk>>>(w_qkv, wqkvT_h, DIM, 3 * DIM);
        transpose_h<<<dim3(DIM / 32, DIM / 32), blk>>>(w_proj, wprojT_h, DIM, DIM);
    }
    // 1) qkv = x @ w_qkv (fp16 in, fp16 out)
    {
        dim3 grid((3 * DIM) / 128, NTOK / 128);
        gemm_h<<<grid, 256, GEMM_SMEM>>>(xh, wqkvT_h, nullptr, qkvh,
                                         NTOK, 3 * DIM, DIM, 1);
    }
    // 2) per-window attention (half I/O) -> [B,H,NW,W,dh] linear
    {
        window_attn_h<<<BATCH * HEADS * NWIN, 128>>>(qkvh, attnh);
    }
    // 3) out = attn_flat @ w_proj + b_proj (fp16 in, fp32 out)
    {
        dim3 grid(DIM / 128, NTOK / 128);
        gemm_h<<<grid, 256, GEMM_SMEM>>>(attnh, wprojT_h, b_proj, out,
                                         NTOK, DIM, DIM, 0);
    }
}

// round 8
// speedup vs baseline: 5.9936x; 1.1985x over previous
#include <cuda_runtime.h>
#include <cuda_fp16.h>
#include <cstdint>

#define DIM     512
#define HEADS   8
#define DH      64
#define BATCH   8
#define NWIN    64
#define WSZ     64
#define NTOK    (BATCH * NWIN * WSZ)   // 32768

// Scratch (allocation-free rule: __device__ globals)
__device__ __half g_xh[(size_t)NTOK * DIM];                       // 33.5 MB
__device__ __half g_qkvh[(size_t)NTOK * 3 * DIM];                 // 100 MB
__device__ __half g_attnh[(size_t)NTOK * DIM];                    // 33.5 MB
__device__ __half g_wth[(size_t)(3 * DIM) * DIM + DIM * DIM];     // 2 MB (wqkvT, wprojT)

// ---------------------------------------------------------------------------
// helpers
// ---------------------------------------------------------------------------
__device__ __forceinline__ uint32_t smem_u32(const void* p) {
    uint32_t a;
    asm("{ .reg .u64 t; cvta.to.shared.u64 t, %1; cvt.u32.u64 %0, t; }"
        : "=r"(a) : "l"(p));
    return a;
}

__device__ __forceinline__ void cp16(uint32_t dst, const void* src) {
    asm volatile("cp.async.cg.shared.global [%0], [%1], 16;"
                 :: "r"(dst), "l"(src) : "memory");
}

__device__ __forceinline__ void ldsm4(unsigned r[4], uint32_t a) {
    asm volatile("ldmatrix.sync.aligned.m8n8.x4.shared.b16 {%0,%1,%2,%3}, [%4];"
                 : "=r"(r[0]), "=r"(r[1]), "=r"(r[2]), "=r"(r[3]) : "r"(a));
}

__device__ __forceinline__ void ldsm4t(unsigned r[4], uint32_t a) {
    asm volatile("ldmatrix.sync.aligned.m8n8.x4.trans.shared.b16 {%0,%1,%2,%3}, [%4];"
                 : "=r"(r[0]), "=r"(r[1]), "=r"(r[2]), "=r"(r[3]) : "r"(a));
}

__device__ __forceinline__ void mma_f16(float c[4], const unsigned a[4],
                                        const unsigned b[2]) {
    asm volatile(
        "mma.sync.aligned.m16n8k16.row.col.f32.f16.f16.f32 "
        "{%0,%1,%2,%3}, {%4,%5,%6,%7}, {%8,%9}, {%0,%1,%2,%3};"
        : "+f"(c[0]), "+f"(c[1]), "+f"(c[2]), "+f"(c[3])
        : "r"(a[0]), "r"(a[1]), "r"(a[2]), "r"(a[3]), "r"(b[0]), "r"(b[1]));
}

// ---------------------------------------------------------------------------
// Prologue: fp32 -> fp16 convert (x), fp32 -> fp16 transpose (weights)
// ---------------------------------------------------------------------------
__global__ void f2h_copy(const float* __restrict__ in, __half* __restrict__ out,
                         int n4)
{
    const int i = blockIdx.x * blockDim.x + threadIdx.x;
    if (i < n4) {
        float4 v = ((const float4*)in)[i];
        __half2* o = (__half2*)(out + (size_t)i * 4);
        o[0] = __floats2half2_rn(v.x, v.y);
        o[1] = __floats2half2_rn(v.z, v.w);
    }
}

__global__ void transpose_h(const float* __restrict__ in,
                            __half* __restrict__ out, int R, int C)
{
    __shared__ float t[32][33];
    const int tx = threadIdx.x, ty = threadIdx.y;
    const int x = blockIdx.x * 32 + tx;
    #pragma unroll
    for (int j = 0; j < 32; j += 8)
        t[ty + j][tx] = in[(size_t)(blockIdx.y * 32 + ty + j) * C + x];
    __syncthreads();
    const int x2 = blockIdx.y * 32 + tx;
    #pragma unroll
    for (int j = 0; j < 32; j += 8)
        out[(size_t)(blockIdx.x * 32 + ty + j) * R + x2] =
            __float2half_rn(t[tx][ty + j]);
}

// ---------------------------------------------------------------------------
// fp16 GEMM: C[M,N] = A[M,K] @ Bt[N,K]^T (+bias).  A, Bt half row-major.
// 128x128 tile, BK=64, 3-stage cp.async, 256 thr / 8 warps (32x64 warp tiles),
// ldmatrix.x4 fragment loads. Stride 72 halves (144B rows): conflict-free.
// ---------------------------------------------------------------------------
#define ST_H      72
#define TILE_H    (128 * ST_H)                 // halves per operand stage
#define NSTAGE    3
#define GEMM_SMEM (NSTAGE * 2 * TILE_H * 2)    // 110592 bytes

__global__ __launch_bounds__(256, 2) void gemm_h(
    const __half* __restrict__ A, const __half* __restrict__ Bt,
    const float* __restrict__ bias, void* __restrict__ Cout,
    int M, int N, int K, int out_half)
{
    extern __shared__ __align__(16) __half smh[];
    __half* As = smh;                       // [3][128][72]
    __half* Bs = smh + NSTAGE * TILE_H;     // [3][128][72]
    const uint32_t as_a = smem_u32(As);
    const uint32_t bs_a = smem_u32(Bs);

    const int tid  = threadIdx.x;
    const int lane = tid & 31;
    const int wid  = tid >> 5;
    const int wm   = (wid & 3) * 32;
    const int wn   = (wid >> 2) * 64;
    const int bm   = blockIdx.y * 128;
    const int bn   = blockIdx.x * 128;
    const int q    = lane & 3;
    const int g    = lane >> 2;

    // per-lane ldmatrix byte offsets within a stage
    const int m8  = lane & 7;
    const int sel = lane >> 3;
    uint32_t a_off[2], b_off[4];
    #pragma unroll
    for (int mt = 0; mt < 2; mt++)
        a_off[mt] = (uint32_t)(((wm + mt * 16 + ((sel & 1) << 3) + m8) * ST_H
                                + ((sel >> 1) << 3)) * 2);
    #pragma unroll
    for (int p = 0; p < 4; p++)
        b_off[p] = (uint32_t)(((wn + ((p << 1) + (sel >> 1)) * 8 + m8) * ST_H
                               + ((sel & 1) << 3)) * 2);

    float acc[2][8][4];
    #pragma unroll
    for (int i = 0; i < 2; i++)
        #pragma unroll
        for (int j = 0; j < 8; j++)
            #pragma unroll
            for (int k = 0; k < 4; k++) acc[i][j][k] = 0.f;

    const int NT = K >> 6;

    #define LOAD_STAGE(kt_)                                                     \
    do {                                                                        \
        const int s_  = (kt_) % NSTAGE;                                         \
        const int k0_ = (kt_) * 64;                                             \
        _Pragma("unroll")                                                       \
        for (int i_ = 0; i_ < 2; i_++) {                                        \
            const int idx_ = tid + i_ * 256;                                    \
            const int row_ = idx_ >> 2;                                         \
            const int c_   = (idx_ & 3) * 16;                                   \
            cp16(as_a + (uint32_t)(s_ * TILE_H + row_ * ST_H + c_) * 2,         \
                 A + (size_t)(bm + row_) * K + k0_ + c_);                       \
            cp16(as_a + (uint32_t)(s_ * TILE_H + row_ * ST_H + c_ + 8) * 2,     \
                 A + (size_t)(bm + row_) * K + k0_ + c_ + 8);                   \
            cp16(bs_a + (uint32_t)(s_ * TILE_H + row_ * ST_H + c_) * 2,         \
                 Bt + (size_t)(bn + row_) * K + k0_ + c_);                      \
            cp16(bs_a + (uint32_t)(s_ * TILE_H + row_ * ST_H + c_ + 8) * 2,     \
                 Bt + (size_t)(bn + row_) * K + k0_ + c_ + 8);                  \
        }                                                                       \
        asm volatile("cp.async.commit_group;" ::: "memory");                    \
    } while (0)

    LOAD_STAGE(0);
    LOAD_STAGE(1);

    for (int kt = 0; kt < NT; kt++) {
        if (kt < NT - 1)
            asm volatile("cp.async.wait_group 1;" ::: "memory");
        else
            asm volatile("cp.async.wait_group 0;" ::: "memory");
        __syncthreads();
        if (kt + 2 < NT) LOAD_STAGE(kt + 2);

        const int st = kt % NSTAGE;
        const uint32_t sa = as_a + (uint32_t)(st * TILE_H) * 2;
        const uint32_t sb = bs_a + (uint32_t)(st * TILE_H) * 2;

        #pragma unroll
        for (int ks = 0; ks < 4; ks++) {
            const uint32_t ko = (uint32_t)(ks * 32);   // 16 halves = 32 bytes
            unsigned afr[2][4], bfr[8][2];
            ldsm4(afr[0], sa + a_off[0] + ko);
            ldsm4(afr[1], sa + a_off[1] + ko);
            #pragma unroll
            for (int p = 0; p < 4; p++) {
                unsigned t[4];
                ldsm4(t, sb + b_off[p] + ko);
                bfr[2 * p][0] = t[0]; bfr[2 * p][1] = t[1];
                bfr[2 * p + 1][0] = t[2]; bfr[2 * p + 1][1] = t[3];
            }
            #pragma unroll
            for (int mt = 0; mt < 2; mt++)
                #pragma unroll
                for (int nt = 0; nt < 8; nt++)
                    mma_f16(acc[mt][nt], afr[mt], bfr[nt]);
        }
    }

    // Epilogue: c0,c1 -> (row g, cols 2q,2q+1); c2,c3 -> row g+8.
    if (out_half) {
        __half* Ch = (__half*)Cout;
        #pragma unroll
        for (int nt = 0; nt < 8; nt++) {
            const int col = bn + wn + nt * 8 + 2 * q;
            #pragma unroll
            for (int mt = 0; mt < 2; mt++) {
                const int r0 = bm + wm + mt * 16 + g;
                *(__half2*)(Ch + (size_t)r0 * N + col) =
                    __floats2half2_rn(acc[mt][nt][0], acc[mt][nt][1]);
                *(__half2*)(Ch + (size_t)(r0 + 8) * N + col) =
                    __floats2half2_rn(acc[mt][nt][2], acc[mt][nt][3]);
            }
        }
    } else {
        float* Cf = (float*)Cout;
        #pragma unroll
        for (int nt = 0; nt < 8; nt++) {
            const int col = bn + wn + nt * 8 + 2 * q;
            float b0 = 0.f, b1 = 0.f;
            if (bias) { b0 = bias[col]; b1 = bias[col + 1]; }
            #pragma unroll
            for (int mt = 0; mt < 2; mt++) {
                const int r0 = bm + wm + mt * 16 + g;
                *(float2*)(Cf + (size_t)r0 * N + col) =
                    make_float2(acc[mt][nt][0] + b0, acc[mt][nt][1] + b1);
                *(float2*)(Cf + (size_t)(r0 + 8) * N + col) =
                    make_float2(acc[mt][nt][2] + b0, acc[mt][nt][3] + b1);
            }
        }
    }
}

// ---------------------------------------------------------------------------
// Window attention: all-fp16 operands, mma.m16n8k16, ldmatrix (+.trans for V).
// One 128-thr block per (b,h,n). Warp w owns rows 16w..16w+15.
// ---------------------------------------------------------------------------
__global__ __launch_bounds__(128) void window_attn_h(
    const __half* __restrict__ qkv, __half* __restrict__ out)
{
    __shared__ __half Qh[64][ST_H];    // Q, then P
    __shared__ __half KVh[64][ST_H];   // K, then V

    const int tid  = threadIdx.x;
    const int lane = tid & 31;
    const int w    = tid >> 5;
    const int g    = lane >> 2;
    const int q    = lane & 3;
    const int m8   = lane & 7;
    const int sel  = lane >> 3;

    const int idx = blockIdx.x;
    const int n   = idx & 63;
    const int h   = (idx >> 6) & 7;
    const int b   = idx >> 9;
    const size_t tokbase = ((size_t)(b * NWIN + n) * WSZ) * (3 * DIM);

    const uint32_t qbase = smem_u32(Qh);
    const uint32_t kbase = smem_u32(KVh);

    // Load Q,K raw half into smem; prefetch V to registers.
    uint4 vpre[4];
    #pragma unroll
    for (int i = 0; i < 4; i++) {
        const int lin = i * 128 + tid;      // 0..511
        const int row = lin >> 3;           // 0..63
        const int c8  = (lin & 7) * 8;      // halves 0..56
        const __half* src = qkv + tokbase + (size_t)row * (3 * DIM) + h * DH + c8;
        *(uint4*)&Qh[row][c8]  = *(const uint4*)src;
        *(uint4*)&KVh[row][c8] = *(const uint4*)(src + DIM);
        vpre[i] = *(const uint4*)(src + 2 * DIM);
    }
    __syncthreads();

    // ldmatrix per-lane offsets (bytes)
    const uint32_t aoff =
        (uint32_t)(((w * 16 + ((sel & 1) << 3) + m8) * ST_H + ((sel >> 1) << 3)) * 2);
    uint32_t boff[4], voff[4];
    #pragma unroll
    for (int p = 0; p < 4; p++) {
        boff[p] = (uint32_t)(((((p << 1) + (sel >> 1)) * 8 + m8) * ST_H
                              + ((sel & 1) << 3)) * 2);
        voff[p] = (uint32_t)(((((sel & 1) << 3) + m8) * ST_H
                              + ((p << 1) + (sel >> 1)) * 8) * 2);
    }

    // S = Q K^T
    float sacc[8][4];
    #pragma unroll
    for (int nt = 0; nt < 8; nt++)
        #pragma unroll
        for (int j = 0; j < 4; j++) sacc[nt][j] = 0.f;

    #pragma unroll
    for (int ks = 0; ks < 4; ks++) {
        const uint32_t ko = (uint32_t)(ks * 32);
        unsigned a[4], bfr[8][2];
        ldsm4(a, qbase + aoff + ko);
        #pragma unroll
        for (int p = 0; p < 4; p++) {
            unsigned t[4];
            ldsm4(t, kbase + boff[p] + ko);
            bfr[2 * p][0] = t[0]; bfr[2 * p][1] = t[1];
            bfr[2 * p + 1][0] = t[2]; bfr[2 * p + 1][1] = t[3];
        }
        #pragma unroll
        for (int nt = 0; nt < 8; nt++)
            mma_f16(sacc[nt], a, bfr[nt]);
    }

    // Register softmax (rows warp-private): thread owns rows r=g(+8), cols 2q..
    const float scale = 0.125f;
    float mx0 = -1e30f, mx1 = -1e30f;
    #pragma unroll
    for (int nt = 0; nt < 8; nt++) {
        #pragma unroll
        for (int j = 0; j < 4; j++) sacc[nt][j] *= scale;
        mx0 = fmaxf(mx0, fmaxf(sacc[nt][0], sacc[nt][1]));
        mx1 = fmaxf(mx1, fmaxf(sacc[nt][2], sacc[nt][3]));
    }
    mx0 = fmaxf(mx0, __shfl_xor_sync(0xffffffffu, mx0, 1));
    mx0 = fmaxf(mx0, __shfl_xor_sync(0xffffffffu, mx0, 2));
    mx1 = fmaxf(mx1, __shfl_xor_sync(0xffffffffu, mx1, 1));
    mx1 = fmaxf(mx1, __shfl_xor_sync(0xffffffffu, mx1, 2));

    float s0 = 0.f, s1 = 0.f;
    #pragma unroll
    for (int nt = 0; nt < 8; nt++) {
        sacc[nt][0] = __expf(sacc[nt][0] - mx0);
        sacc[nt][1] = __expf(sacc[nt][1] - mx0);
        sacc[nt][2] = __expf(sacc[nt][2] - mx1);
        sacc[nt][3] = __expf(sacc[nt][3] - mx1);
        s0 += sacc[nt][0] + sacc[nt][1];
        s1 += sacc[nt][2] + sacc[nt][3];
    }
    s0 += __shfl_xor_sync(0xffffffffu, s0, 1);
    s0 += __shfl_xor_sync(0xffffffffu, s0, 2);
    s1 += __shfl_xor_sync(0xffffffffu, s1, 1);
    s1 += __shfl_xor_sync(0xffffffffu, s1, 2);
    const float inv0 = 1.f / s0, inv1 = 1.f / s1;

    // P -> Qh (half, warp-private rows)
    {
        const int r = w * 16 + g;
        #pragma unroll
        for (int nt = 0; nt < 8; nt++) {
            const int col = nt * 8 + 2 * q;
            *(__half2*)&Qh[r][col] =
                __floats2half2_rn(sacc[nt][0] * inv0, sacc[nt][1] * inv0);
            *(__half2*)&Qh[r + 8][col] =
                __floats2half2_rn(sacc[nt][2] * inv1, sacc[nt][3] * inv1);
        }
    }
    __syncthreads();   // all warps' K reads complete before V overwrites KVh

    // V -> KVh (raw half)
    #pragma unroll
    for (int i = 0; i < 4; i++) {
        const int lin = i * 128 + tid;
        const int row = lin >> 3;
        const int c8  = (lin & 7) * 8;
        *(uint4*)&KVh[row][c8] = vpre[i];
    }
    __syncthreads();

    // O = P V  (V via ldmatrix.trans)
    float oacc[8][4];
    #pragma unroll
    for (int nt = 0; nt < 8; nt++)
        #pragma unroll
        for (int j = 0; j < 4; j++) oacc[nt][j] = 0.f;

    #pragma unroll
    for (int ks = 0; ks < 4; ks++) {
        const uint32_t ko  = (uint32_t)(ks * 32);               // P: +16 cols
        const uint32_t kov = (uint32_t)(ks * 16 * ST_H * 2);    // V: +16 rows
        unsigned a[4], bfr[8][2];
        ldsm4(a, qbase + aoff + ko);
        #pragma unroll
        for (int p = 0; p < 4; p++) {
            unsigned t[4];
            ldsm4t(t, kbase + voff[p] + kov);
            bfr[2 * p][0] = t[0]; bfr[2 * p][1] = t[1];
            bfr[2 * p + 1][0] = t[2]; bfr[2 * p + 1][1] = t[3];
        }
        #pragma unroll
        for (int nt = 0; nt < 8; nt++)
            mma_f16(oacc[nt], a, bfr[nt]);
    }

    // O -> half, [B,H,NW,W,dh] linear layout (free reshape for proj GEMM)
    const size_t obase = (((size_t)(b * HEADS + h) * NWIN + n) * WSZ) * DH;
    const int r = w * 16 + g;
    #pragma unroll
    for (int nt = 0; nt < 8; nt++) {
        const int col = nt * 8 + 2 * q;
        *(__half2*)(out + obase + (size_t)r * DH + col) =
            __floats2half2_rn(oacc[nt][0], oacc[nt][1]);
        *(__half2*)(out + obase + (size_t)(r + 8) * DH + col) =
            __floats2half2_rn(oacc[nt][2], oacc[nt][3]);
    }
}

// ---------------------------------------------------------------------------
extern "C" void kernel_launch(void* const* d_in, const int* in_sizes, int n_in,
                              void* d_out, int out_size)
{
    const float* x      = (const float*)d_in[0];  // [8,64,64,512]
    const float* w_qkv  = (const float*)d_in[1];  // [512,1536]
    const float* w_proj = (const float*)d_in[2];  // [512,512]
    const float* b_proj = (const float*)d_in[3];  // [512]
    float* out = (float*)d_out;                   // [8,64,64,512]

    __half *xh, *qkvh, *attnh, *wth;
    cudaGetSymbolAddress((void**)&xh,    g_xh);
    cudaGetSymbolAddress((void**)&qkvh,  g_qkvh);
    cudaGetSymbolAddress((void**)&attnh, g_attnh);
    cudaGetSymbolAddress((void**)&wth,   g_wth);
    __half* wqkvT_h  = wth;                            // [1536,512]
    __half* wprojT_h = wth + (size_t)(3 * DIM) * DIM;  // [512,512]

    static bool attr_set = false;
    if (!attr_set) {
        cudaFuncSetAttribute(gemm_h,
                             cudaFuncAttributeMaxDynamicSharedMemorySize, GEMM_SMEM);
        attr_set = true;
    }

    // 0) prologue: x -> half; weights -> transposed half
    {
        const int n4 = NTOK * DIM / 4;
        f2h_copy<<<(n4 + 255) / 256, 256>>>(x, xh, n4);
        dim3 blk(32, 8);
        transpose_h<<<dim3((3 * DIM) / 32, DIM / 32), blk>>>(w_qkv, wqkvT_h, DIM, 3 * DIM);
        transpose_h<<<dim3(DIM / 32, DIM / 32), blk>>>(w_proj, wprojT_h, DIM, DIM);
    }
    // 1) qkv = x @ w_qkv (fp16 in, fp16 out)
    {
        dim3 grid((3 * DIM) / 128, NTOK / 128);
        gemm_h<<<grid, 256, GEMM_SMEM>>>(xh, wqkvT_h, nullptr, qkvh,
                                         NTOK, 3 * DIM, DIM, 1);
    }
    // 2) per-window attention -> [B,H,NW,W,dh] linear
    {
        window_attn_h<<<BATCH * HEADS * NWIN, 128>>>(qkvh, attnh);
    }
    // 3) out = attn_flat @ w_proj + b_proj (fp16 in, fp32 out)
    {
        dim3 grid(DIM / 128, NTOK / 128);
        gemm_h<<<grid, 256, GEMM_SMEM>>>(attnh, wprojT_h, b_proj, out,
                                         NTOK, DIM, DIM, 0);
    }
}